// round 13
// baseline (speedup 1.0000x reference)
#include <cuda_runtime.h>
#include <cstdint>
#include <math.h>

#define SEQ 2048
#define DH  64
#define BQ  128
#define BK  64
#define NT  (SEQ/BK)
#define SCALEF 0.03125f

#define ST_Q 68
#define ST_P 68
#define ST_K 68
#define ST_V 72

// smem float offsets
#define F_MSK 0
#define F_QS  2048
#define F_P   (F_QS + BQ*ST_Q)
#define F_KS  (F_P  + BQ*ST_P)
#define F_VS  (F_KS + BK*ST_K)
#define SMEM_FLOATS (F_VS + BK*ST_V)
#define SMEM_BYTES  (SMEM_FLOATS*4)

static __device__ __forceinline__ uint32_t f2t(float x){
    uint32_t r; asm("cvt.rna.tf32.f32 %0, %1;" : "=r"(r) : "f"(x)); return r;
}
static __device__ __forceinline__ void mma8(float c[4], const uint32_t a[4],
                                            uint32_t b0, uint32_t b1){
    asm volatile("mma.sync.aligned.m16n8k8.row.col.f32.tf32.tf32.f32 "
        "{%0,%1,%2,%3}, {%4,%5,%6,%7}, {%8,%9}, {%0,%1,%2,%3};"
        : "+f"(c[0]),"+f"(c[1]),"+f"(c[2]),"+f"(c[3])
        : "r"(a[0]),"r"(a[1]),"r"(a[2]),"r"(a[3]), "r"(b0),"r"(b1));
}

// k-interleave staging: lane-pair exchange so that logical k-cols (t, t+4) of
// each 8-group are physically adjacent. Even-g lane holds logical {c4..c4+3} of
// a group (-> phys {0,2,4,6}+base), odd-g lane holds {c4..c4+3} = group's
// {4..7} (-> phys {1,3,5,7}+base). After exchanging two floats with lane^1,
// both lanes store one physical float4 with STS.128 at the SAME c4 offset.
static __device__ __forceinline__ uint4 ileave(float4 v, int odd){
    float s0 = odd ? v.x : v.z;
    float s1 = odd ? v.y : v.w;
    float r0 = __shfl_xor_sync(0xffffffffu, s0, 1);
    float r1 = __shfl_xor_sync(0xffffffffu, s1, 1);
    uint4 u;
    if (!odd){ u.x=f2t(v.x); u.y=f2t(r0); u.z=f2t(v.y); u.w=f2t(r1); }
    else     { u.x=f2t(r0);  u.y=f2t(v.z); u.z=f2t(r1); u.w=f2t(v.w); }
    return u;
}

__global__ __launch_bounds__(256,2)
void attn_mma3_kernel(const float* __restrict__ Q, const float* __restrict__ K,
                      const float* __restrict__ V, const int* __restrict__ mask,
                      float* __restrict__ O)
{
    extern __shared__ float sm[];
    uint32_t* usm = (uint32_t*)sm;
    const int tid  = threadIdx.x;
    const int wid  = tid >> 5, lane = tid & 31;
    const int gid  = lane >> 2, tig = lane & 3;
    const int rA   = (wid << 4) + gid, rB = rA + 8;

    const int qt = blockIdx.x, bh = blockIdx.y, b = bh >> 4;
    const float* Qg = Q + ((size_t)bh*SEQ + (size_t)qt*BQ)*DH;
    const float* Kg = K + (size_t)bh*SEQ*DH;
    const float* Vg = V + (size_t)bh*SEQ*DH;
    const int*   Mg = mask + (size_t)b*SEQ;
    float*       Og = O + ((size_t)bh*SEQ + (size_t)qt*BQ)*DH;

    // ---- preload mask row as float (once) ----
    #pragma unroll
    for (int i = tid; i < SEQ; i += 256) sm[F_MSK + i] = (float)Mg[i];

    // ---- stage Q (tf32, k-interleaved, stride 68, STS.128) ----
    {
        const float4* Qg4 = (const float4*)Qg;
        #pragma unroll
        for (int p = 0; p < 8; ++p){
            int f = tid + p*256;
            float4 q4 = Qg4[f];
            int row = f >> 4, c4 = (f & 15) * 4;
            *(uint4*)(usm + F_QS + row*ST_Q + c4) = ileave(q4, f & 1);
        }
    }

    // ---- prefetch tile 0 K/V ----
    float4 kreg[4], vreg[4];
    {
        const float4* Kg4 = (const float4*)Kg;
        const float4* Vg4 = (const float4*)Vg;
        #pragma unroll
        for (int p=0;p<4;++p){ kreg[p]=Kg4[tid+p*256]; vreg[p]=Vg4[tid+p*256]; }
    }

    float o[8][4];
    float lsum0 = 0.f, lsum1 = 0.f;
    #pragma unroll
    for (int j=0;j<8;++j){ o[j][0]=o[j][1]=o[j][2]=o[j][3]=0.f; }

    for (int kt = 0; kt < NT; ++kt){
        if (kt) __syncthreads();    // prev PV done reading Ks/Vs

        // ---- store K (k-interleaved, stride 68) / V (logical, stride 72) ----
        #pragma unroll
        for (int p=0;p<4;++p){
            int f = tid + p*256;
            int row = f >> 4, c4 = (f & 15) * 4;
            *(uint4*)(usm + F_KS + row*ST_K + c4) = ileave(kreg[p], f & 1);
            uint4 vu = { f2t(vreg[p].x), f2t(vreg[p].y), f2t(vreg[p].z), f2t(vreg[p].w) };
            *(uint4*)(usm + F_VS + row*ST_V + c4) = vu;
        }
        __syncthreads();

        // ---- S = Q K^T : 8 s-steps x 8 j-tiles; LDS.64 fragment feeds ----
        float s_[8][4];
        #pragma unroll
        for (int j=0;j<8;++j){ s_[j][0]=s_[j][1]=s_[j][2]=s_[j][3]=0.f; }
        #pragma unroll
        for (int s=0;s<8;++s){
            uint32_t qa[4];
            uint2 qlo = *(const uint2*)(usm + F_QS + rA*ST_Q + 8*s + 2*tig);
            uint2 qhi = *(const uint2*)(usm + F_QS + rB*ST_Q + 8*s + 2*tig);
            qa[0]=qlo.x; qa[2]=qlo.y; qa[1]=qhi.x; qa[3]=qhi.y;
            #pragma unroll
            for (int j=0;j<8;++j){
                uint2 kb = *(const uint2*)(usm + F_KS + (8*j+gid)*ST_K + 8*s + 2*tig);
                mma8(s_[j], qa, kb.x, kb.y);
            }
        }

        // ---- softmax + write P (tf32, logical order, stride 68) ----
        const float* mrow = sm + F_MSK + kt*BK;
        #pragma unroll
        for (int j=0;j<8;++j){
            float2 mk = *(const float2*)(mrow + 8*j + 2*tig);
            float p0 = mk.x * __expf(s_[j][0]*SCALEF);
            float p1 = mk.y * __expf(s_[j][1]*SCALEF);
            float p2 = mk.x * __expf(s_[j][2]*SCALEF);
            float p3 = mk.y * __expf(s_[j][3]*SCALEF);
            lsum0 += p0 + p1;
            lsum1 += p2 + p3;
            uint2 uA = { f2t(p0), f2t(p1) };
            uint2 uB = { f2t(p2), f2t(p3) };
            *(uint2*)(usm + F_P + rA*ST_P + 8*j + 2*tig) = uA;
            *(uint2*)(usm + F_P + rB*ST_P + 8*j + 2*tig) = uB;
        }

        // ---- prefetch next K/V (covered by PV below) ----
        if (kt + 1 < NT){
            const float4* Kg4 = (const float4*)(Kg + (size_t)(kt+1)*BK*DH);
            const float4* Vg4 = (const float4*)(Vg + (size_t)(kt+1)*BK*DH);
            #pragma unroll
            for (int p=0;p<4;++p){ kreg[p]=Kg4[tid+p*256]; vreg[p]=Vg4[tid+p*256]; }
        }

        // ---- O += P V : 8 sk-chunks x 8 d-tiles (logical k order) ----
        #pragma unroll
        for (int sk=0;sk<8;++sk){
            uint32_t pa[4];
            const uint32_t* pb = usm + F_P + rA*ST_P + 8*sk + tig;
            pa[0]=pb[0]; pa[1]=pb[8*ST_P]; pa[2]=pb[4]; pa[3]=pb[8*ST_P+4];
            #pragma unroll
            for (int jd=0;jd<8;++jd){
                const uint32_t* vb = usm + F_VS + (8*sk+tig)*ST_V + 8*jd + gid;
                mma8(o[jd], pa, vb[0], vb[4*ST_V]);
            }
        }
    }

    // ---- epilogue ----
    lsum0 += __shfl_xor_sync(0xffffffffu, lsum0, 1);
    lsum0 += __shfl_xor_sync(0xffffffffu, lsum0, 2);
    lsum1 += __shfl_xor_sync(0xffffffffu, lsum1, 1);
    lsum1 += __shfl_xor_sync(0xffffffffu, lsum1, 2);
    float inv0 = 1.f / lsum0, inv1 = 1.f / lsum1;

    #pragma unroll
    for (int jd=0;jd<8;++jd){
        float2 w0 = make_float2(o[jd][0]*inv0, o[jd][1]*inv0);
        float2 w1 = make_float2(o[jd][2]*inv1, o[jd][3]*inv1);
        *(float2*)(Og + (size_t)rA*DH + 8*jd + 2*tig) = w0;
        *(float2*)(Og + (size_t)rB*DH + 8*jd + 2*tig) = w1;
    }
}

extern "C" void kernel_launch(void* const* d_in, const int* in_sizes, int n_in,
                              void* d_out, int out_size)
{
    const float* q = (const float*)d_in[0];
    const float* k = (const float*)d_in[1];
    const float* v = (const float*)d_in[2];
    const int*   m = (const int*)d_in[3];
    float* out = (float*)d_out;

    cudaFuncSetAttribute(attn_mma3_kernel,
                         cudaFuncAttributeMaxDynamicSharedMemorySize, SMEM_BYTES);

    dim3 grid(SEQ / BQ, 32);
    dim3 block(256);
    attn_mma3_kernel<<<grid, block, SMEM_BYTES>>>(q, k, v, m, out);
}